// round 15
// baseline (speedup 1.0000x reference)
#include <cuda_runtime.h>

// DDLG autoencoder, fully fused, full fp32. Activations in SMEM as float4
// packing FOUR batch rows per column (quad layout, 16B/col). Each lane owns
// one neuron x 4 rows: one LDS.128 per connection. Gate recurrences run as
// packed f32x2 FFMA2 (fma.rn.f32x2) on two row-pairs -> half the fma slots
// at full fp32 precision. sizes: 4096 -> 2048 -> 1024 -> 2048 -> 4096.

#define BATCH 4096
#define F0 4096
#define O0 2048
#define O1 1024
#define O2 2048
#define O3 4096
#define TOTAL_O (O0 + O1 + O2 + O3)

#define RPB 4            // batch rows per block (one quad)
#define THREADS 512      // 16 warps; 2 blocks/SM, 64-reg cap (no spill headroom issues)
#define SMEM_BYTES ((F0 * 4 + O0 * 4) * 4)   // bufA 64KB + bufB 32KB = 96KB

// ---- packed f32x2 macros (ptx_helpers.cuh style: output-parameter asm) ----
#define FMA_F32X2(out, a, b, c) \
    asm("fma.rn.f32x2 %0, %1, %2, %3;" : "=l"(out) : "l"(a), "l"(b), "l"(c))
#define PACK_F32X2(out, lo, hi) \
    asm("mov.b64 %0, {%1, %2};" : "=l"(out) : "f"(lo), "f"(hi))
#define UNPACK_F32X2(lo, hi, in) \
    asm("mov.b64 {%0, %1}, %2;" : "=f"(lo), "=f"(hi) : "l"(in))

// per-neuron mixing probabilities (softmax(w) or one-hot), precomputed
__device__ float g_probs[TOTAL_O * 4];

__global__ void prob_kernel(const float* __restrict__ w0, const float* __restrict__ w1,
                            const float* __restrict__ w2, const float* __restrict__ w3,
                            const int* __restrict__ is_train) {
    int t = blockIdx.x * blockDim.x + threadIdx.x;
    if (t >= TOTAL_O) return;
    const float* w;
    if (t < O0)                w = w0 + t * 4;
    else if (t < O0 + O1)      w = w1 + (t - O0) * 4;
    else if (t < O0 + O1 + O2) w = w2 + (t - O0 - O1) * 4;
    else                       w = w3 + (t - O0 - O1 - O2) * 4;
    float a = w[0], b = w[1], c = w[2], d = w[3];
    float p0, p1, p2, p3;
    if (*is_train != 0) {
        float m = fmaxf(fmaxf(a, b), fmaxf(c, d));
        float ea = __expf(a - m), eb = __expf(b - m);
        float ec = __expf(c - m), ed = __expf(d - m);
        float inv = __fdividef(1.0f, ea + eb + ec + ed);
        p0 = ea * inv; p1 = eb * inv; p2 = ec * inv; p3 = ed * inv;
    } else {
        int k = 0; float best = a;
        if (b > best) { best = b; k = 1; }
        if (c > best) { best = c; k = 2; }
        if (d > best) { best = d; k = 3; }
        p0 = (k == 0) ? 1.0f : 0.0f;
        p1 = (k == 1) ? 1.0f : 0.0f;
        p2 = (k == 2) ? 1.0f : 0.0f;
        p3 = (k == 3) ? 1.0f : 0.0f;
    }
    *(float4*)(g_probs + t * 4) = make_float4(p0, p1, p2, p3);
}

// One neuron x 4 rows (one float4 quad per connection, LDS.128).
// coein fold as rational:  N'=fma(b,D,N), D'=fma(b,N,D)  [packed f32x2].
// ein via De Morgan on complements u = fma(b,-1,1): same recurrence;
// ein = (Da-Na)/Da. min/max scalar FMNMX. One reciprocal per row at the end.
__device__ __forceinline__ float4 neuron4f(const float4* __restrict__ bufIn,
                                           const int* __restrict__ idxp,
                                           const float* __restrict__ probp) {
    int4 i0 = __ldg((const int4*)idxp);
    int4 i1 = __ldg(((const int4*)idxp) + 1);
    float4 p = __ldg((const float4*)probp);

    float4 v0 = bufIn[i0.x];
    float4 v1 = bufIn[i0.y];
    float4 v2 = bufIn[i0.z];
    float4 v3 = bufIn[i0.w];
    float4 v4 = bufIn[i1.x];
    float4 v5 = bufIn[i1.y];
    float4 v6 = bufIn[i1.z];
    float4 v7 = bufIn[i1.w];

    unsigned long long one2, neg2;
    PACK_F32X2(one2, 1.0f, 1.0f);
    PACK_F32X2(neg2, -1.0f, -1.0f);

    float mn0 = v0.x, mx0 = v0.x, mn1 = v0.y, mx1 = v0.y;
    float mn2 = v0.z, mx2 = v0.z, mn3 = v0.w, mx3 = v0.w;

    unsigned long long blv, bhv;
    PACK_F32X2(blv, v0.x, v0.y);
    PACK_F32X2(bhv, v0.z, v0.w);
    unsigned long long NaL, DaL, NcL, DcL, NaH, DaH, NcH, DcH;
    FMA_F32X2(NaL, blv, neg2, one2);
    FMA_F32X2(NaH, bhv, neg2, one2);
    DaL = one2; NcL = blv; DcL = one2;
    DaH = one2; NcH = bhv; DcH = one2;

#define DDLG_STEP(wv)                                                   \
    {                                                                   \
        mn0 = fminf(mn0, (wv).x); mx0 = fmaxf(mx0, (wv).x);             \
        mn1 = fminf(mn1, (wv).y); mx1 = fmaxf(mx1, (wv).y);             \
        mn2 = fminf(mn2, (wv).z); mx2 = fmaxf(mx2, (wv).z);             \
        mn3 = fminf(mn3, (wv).w); mx3 = fmaxf(mx3, (wv).w);             \
        unsigned long long bl_, bh_, ul_, uh_, t_;                      \
        PACK_F32X2(bl_, (wv).x, (wv).y);                                \
        PACK_F32X2(bh_, (wv).z, (wv).w);                                \
        FMA_F32X2(ul_, bl_, neg2, one2);                                \
        FMA_F32X2(uh_, bh_, neg2, one2);                                \
        FMA_F32X2(t_, ul_, DaL, NaL);                                   \
        FMA_F32X2(DaL, ul_, NaL, DaL);                                  \
        NaL = t_;                                                       \
        FMA_F32X2(t_, uh_, DaH, NaH);                                   \
        FMA_F32X2(DaH, uh_, NaH, DaH);                                  \
        NaH = t_;                                                       \
        FMA_F32X2(t_, bl_, DcL, NcL);                                   \
        FMA_F32X2(DcL, bl_, NcL, DcL);                                  \
        NcL = t_;                                                       \
        FMA_F32X2(t_, bh_, DcH, NcH);                                   \
        FMA_F32X2(DcH, bh_, NcH, DcH);                                  \
        NcH = t_;                                                       \
    }

    DDLG_STEP(v1) DDLG_STEP(v2) DDLG_STEP(v3) DDLG_STEP(v4)
    DDLG_STEP(v5) DDLG_STEP(v6) DDLG_STEP(v7)
#undef DDLG_STEP

    // ein numerator: e = Da - Na = fma(Na, -1, Da) (packed)
    unsigned long long eL, eH;
    FMA_F32X2(eL, NaL, neg2, DaL);
    FMA_F32X2(eH, NaH, neg2, DaH);

    float el0, el1, eh0, eh1, dal0, dal1, dah0, dah1;
    float ncl0, ncl1, nch0, nch1, dcl0, dcl1, dch0, dch1;
    UNPACK_F32X2(el0, el1, eL);
    UNPACK_F32X2(eh0, eh1, eH);
    UNPACK_F32X2(dal0, dal1, DaL);
    UNPACK_F32X2(dah0, dah1, DaH);
    UNPACK_F32X2(ncl0, ncl1, NcL);
    UNPACK_F32X2(nch0, nch1, NcH);
    UNPACK_F32X2(dcl0, dcl1, DcL);
    UNPACK_F32X2(dch0, dch1, DcH);

    float num0 = fmaf(p.z * el0, dcl0, (p.w * ncl0) * dal0);
    float r0 = fmaf(p.x, mn0, fmaf(p.y, mx0, __fdividef(num0, dal0 * dcl0)));
    float num1 = fmaf(p.z * el1, dcl1, (p.w * ncl1) * dal1);
    float r1 = fmaf(p.x, mn1, fmaf(p.y, mx1, __fdividef(num1, dal1 * dcl1)));
    float num2 = fmaf(p.z * eh0, dch0, (p.w * nch0) * dah0);
    float r2 = fmaf(p.x, mn2, fmaf(p.y, mx2, __fdividef(num2, dah0 * dch0)));
    float num3 = fmaf(p.z * eh1, dch1, (p.w * nch1) * dah1);
    float r3 = fmaf(p.x, mn3, fmaf(p.y, mx3, __fdividef(num3, dah1 * dch1)));

    return make_float4(r0, r1, r2, r3);
}

// Each thread owns one neuron (all 4 rows). Consecutive o per lane ->
// idx/probs LDG fully coalesced; STS.128 output at consecutive columns.
__device__ __forceinline__ void layer4f(const float4* __restrict__ bufIn,
                                        float4* __restrict__ bufOut,
                                        const int* __restrict__ idx,
                                        const float* __restrict__ probs, int O) {
    for (int o = threadIdx.x; o < O; o += THREADS) {
        bufOut[o] = neuron4f(bufIn, idx + o * 8, probs + o * 4);
    }
}

__global__ void __launch_bounds__(THREADS, 2)
ddlg_kernel(const float* __restrict__ x,
            const int* __restrict__ idx0, const int* __restrict__ idx1,
            const int* __restrict__ idx2, const int* __restrict__ idx3,
            float* __restrict__ out) {
    extern __shared__ float smf[];
    float4* bufA = (float4*)smf;             // 4096 columns x 4 rows
    float4* bufB = (float4*)(smf + F0 * 4);  // 2048 columns x 4 rows

    const int rowBase = blockIdx.x * RPB;

    // Transpose 4 rows of x into quad layout (coalesced row reads, STS.128).
    {
        const float* x0 = x + (size_t)rowBase * F0;
        for (int c = threadIdx.x; c < F0; c += THREADS) {
            float4 v;
            v.x = x0[c];
            v.y = x0[F0 + c];
            v.z = x0[2 * F0 + c];
            v.w = x0[3 * F0 + c];
            bufA[c] = v;
        }
    }
    __syncthreads();

    layer4f(bufA, bufB, idx0, g_probs, O0);
    __syncthreads();
    layer4f(bufB, bufA, idx1, g_probs + O0 * 4, O1);
    __syncthreads();
    layer4f(bufA, bufB, idx2, g_probs + (O0 + O1) * 4, O2);
    __syncthreads();
    layer4f(bufB, bufA, idx3, g_probs + (O0 + O1 + O2) * 4, O3);
    __syncthreads();

    // Un-quad bufA into 4 coalesced fp32 output rows.
    {
        float* o0 = out + (size_t)rowBase * O3;
        for (int c = threadIdx.x; c < O3; c += THREADS) {
            float4 v = bufA[c];
            o0[c] = v.x;
            o0[O3 + c] = v.y;
            o0[2 * O3 + c] = v.z;
            o0[3 * O3 + c] = v.w;
        }
    }
}

extern "C" void kernel_launch(void* const* d_in, const int* in_sizes, int n_in,
                              void* d_out, int out_size) {
    const float* x   = (const float*)d_in[0];
    const float* w0  = (const float*)d_in[1];
    const float* w1  = (const float*)d_in[2];
    const float* w2  = (const float*)d_in[3];
    const float* w3  = (const float*)d_in[4];
    const int* idx0  = (const int*)d_in[5];
    const int* idx1  = (const int*)d_in[6];
    const int* idx2  = (const int*)d_in[7];
    const int* idx3  = (const int*)d_in[8];
    const int* is_tr = (const int*)d_in[9];
    float* out = (float*)d_out;

    cudaFuncSetAttribute(ddlg_kernel, cudaFuncAttributeMaxDynamicSharedMemorySize, SMEM_BYTES);

    prob_kernel<<<(TOTAL_O + 255) / 256, 256>>>(w0, w1, w2, w3, is_tr);
    ddlg_kernel<<<BATCH / RPB, THREADS, SMEM_BYTES>>>(x, idx0, idx1, idx2, idx3, out);
}